// round 12
// baseline (speedup 1.0000x reference)
#include <cuda_runtime.h>
#include <math.h>
#include <stdint.h>

#define T_ 1024
#define B_ 8
#define E_ 512
#define H_ 8
#define D_ 64
#define S_ 2048
#define LDK 20
#define LDV 72

// ---------------- scratch (device globals; no allocations) ----------------
__device__ float g_qin[T_ * B_ * E_];                 // (t,b,e)
__device__ float g_q[B_ * H_ * T_ * D_];              // (b,h,t,d)
__device__ float g_k[B_ * H_ * S_ * D_];              // (b,h,s,d)
__device__ float g_v[B_ * H_ * S_ * D_];              // (b,h,s,d)
__device__ float g_p[(size_t)B_ * H_ * T_ * S_];      // (b,h,t,s)
__device__ float g_attn[T_ * B_ * E_];                // (t,b, h*64+d)

// ---------------- tf32 helpers ----------------
__device__ __forceinline__ uint32_t f2tf32(float x) {
    uint32_t r;
    asm("cvt.rna.tf32.f32 %0, %1;" : "=r"(r) : "f"(x));
    return r;
}

__device__ __forceinline__ void mma8(float c[4],
                                     uint32_t a0, uint32_t a1, uint32_t a2, uint32_t a3,
                                     uint32_t b0, uint32_t b1) {
    asm volatile(
        "mma.sync.aligned.m16n8k8.row.col.f32.tf32.tf32.f32 "
        "{%0,%1,%2,%3},{%4,%5,%6,%7},{%8,%9},{%0,%1,%2,%3};"
        : "+f"(c[0]), "+f"(c[1]), "+f"(c[2]), "+f"(c[3])
        : "r"(a0), "r"(a1), "r"(a2), "r"(a3), "r"(b0), "r"(b1));
}

// ---------------- staging: 128 rows x 16 cols fp32 -> smem tf32 (hi[,lo]) ----------------
__device__ __forceinline__ void stage3(const float* __restrict__ src, int ld,
                                       float (*dh)[LDK], float (*dl)[LDK]) {
    int r = threadIdx.x >> 1, c = (threadIdx.x & 1) << 3;
    const float* p = src + (size_t)r * ld + c;
    float4 v0 = *(const float4*)p;
    float4 v1 = *(const float4*)(p + 4);
    float v[8] = {v0.x, v0.y, v0.z, v0.w, v1.x, v1.y, v1.z, v1.w};
    float h[8], l[8];
    #pragma unroll
    for (int i = 0; i < 8; i++) {
        h[i] = __uint_as_float(f2tf32(v[i]));
        l[i] = __uint_as_float(f2tf32(v[i] - h[i]));
    }
    *(float4*)&dh[r][c]     = make_float4(h[0], h[1], h[2], h[3]);
    *(float4*)&dh[r][c + 4] = make_float4(h[4], h[5], h[6], h[7]);
    *(float4*)&dl[r][c]     = make_float4(l[0], l[1], l[2], l[3]);
    *(float4*)&dl[r][c + 4] = make_float4(l[4], l[5], l[6], l[7]);
}

__device__ __forceinline__ void stage1(const float* __restrict__ src, int ld,
                                       float (*dh)[LDK]) {
    int r = threadIdx.x >> 1, c = (threadIdx.x & 1) << 3;
    const float* p = src + (size_t)r * ld + c;
    float4 v0 = *(const float4*)p;
    float4 v1 = *(const float4*)(p + 4);
    float v[8] = {v0.x, v0.y, v0.z, v0.w, v1.x, v1.y, v1.z, v1.w};
    float h[8];
    #pragma unroll
    for (int i = 0; i < 8; i++) h[i] = __uint_as_float(f2tf32(v[i]));
    *(float4*)&dh[r][c]     = make_float4(h[0], h[1], h[2], h[3]);
    *(float4*)&dh[r][c + 4] = make_float4(h[4], h[5], h[6], h[7]);
}

// ---------------- 128x128 block: acc += A(128x16) * B(128x16)^T, 3xTF32 ----------------
__device__ __forceinline__ void mma_block3(float (*Ah)[LDK], float (*Al)[LDK],
                                           float (*Bh)[LDK], float (*Bl)[LDK],
                                           float acc[4][4][4]) {
    const int lane = threadIdx.x & 31, warp = threadIdx.x >> 5;
    const int wm = warp >> 2, wn = warp & 3;
    const int gid = lane >> 2, t4 = lane & 3;
    #pragma unroll
    for (int kk = 0; kk < 16; kk += 8) {
        uint32_t ah[4][4], al[4][4];
        #pragma unroll
        for (int mi = 0; mi < 4; mi++) {
            int r = wm * 64 + mi * 16 + gid;
            ah[mi][0] = __float_as_uint(Ah[r][kk + t4]);
            ah[mi][1] = __float_as_uint(Ah[r + 8][kk + t4]);
            ah[mi][2] = __float_as_uint(Ah[r][kk + t4 + 4]);
            ah[mi][3] = __float_as_uint(Ah[r + 8][kk + t4 + 4]);
            al[mi][0] = __float_as_uint(Al[r][kk + t4]);
            al[mi][1] = __float_as_uint(Al[r + 8][kk + t4]);
            al[mi][2] = __float_as_uint(Al[r][kk + t4 + 4]);
            al[mi][3] = __float_as_uint(Al[r + 8][kk + t4 + 4]);
        }
        #pragma unroll
        for (int ni = 0; ni < 4; ni++) {
            int c = wn * 32 + ni * 8 + gid;
            uint32_t bh0 = __float_as_uint(Bh[c][kk + t4]);
            uint32_t bh1 = __float_as_uint(Bh[c][kk + t4 + 4]);
            uint32_t bl0 = __float_as_uint(Bl[c][kk + t4]);
            uint32_t bl1 = __float_as_uint(Bl[c][kk + t4 + 4]);
            #pragma unroll
            for (int mi = 0; mi < 4; mi++) {
                mma8(acc[mi][ni], ah[mi][0], ah[mi][1], ah[mi][2], ah[mi][3], bh0, bh1);
                mma8(acc[mi][ni], ah[mi][0], ah[mi][1], ah[mi][2], ah[mi][3], bl0, bl1);
                mma8(acc[mi][ni], al[mi][0], al[mi][1], al[mi][2], al[mi][3], bh0, bh1);
            }
        }
    }
}

// 1-pass version
__device__ __forceinline__ void mma_block1(float (*Ah)[LDK], float (*Bh)[LDK],
                                           float acc[4][4][4]) {
    const int lane = threadIdx.x & 31, warp = threadIdx.x >> 5;
    const int wm = warp >> 2, wn = warp & 3;
    const int gid = lane >> 2, t4 = lane & 3;
    #pragma unroll
    for (int kk = 0; kk < 16; kk += 8) {
        uint32_t ah[4][4];
        #pragma unroll
        for (int mi = 0; mi < 4; mi++) {
            int r = wm * 64 + mi * 16 + gid;
            ah[mi][0] = __float_as_uint(Ah[r][kk + t4]);
            ah[mi][1] = __float_as_uint(Ah[r + 8][kk + t4]);
            ah[mi][2] = __float_as_uint(Ah[r][kk + t4 + 4]);
            ah[mi][3] = __float_as_uint(Ah[r + 8][kk + t4 + 4]);
        }
        #pragma unroll
        for (int ni = 0; ni < 4; ni++) {
            int c = wn * 32 + ni * 8 + gid;
            uint32_t bh0 = __float_as_uint(Bh[c][kk + t4]);
            uint32_t bh1 = __float_as_uint(Bh[c][kk + t4 + 4]);
            #pragma unroll
            for (int mi = 0; mi < 4; mi++)
                mma8(acc[mi][ni], ah[mi][0], ah[mi][1], ah[mi][2], ah[mi][3], bh0, bh1);
        }
    }
}

// ---------------- q_in = shift(fwd,+1) + shift(bwd,-1), float4 ----------------
__global__ void build_qin_kernel(const float* __restrict__ fwd,
                                 const float* __restrict__ bwd) {
    int i4 = blockIdx.x * blockDim.x + threadIdx.x;    // over T*B*E/4
    int idx = i4 << 2;
    int t = idx / (B_ * E_);
    float4 v = make_float4(0.f, 0.f, 0.f, 0.f);
    if (t > 0) {
        float4 a = *(const float4*)(fwd + idx - B_ * E_);
        v.x += a.x; v.y += a.y; v.z += a.z; v.w += a.w;
    }
    if (t < T_ - 1) {
        float4 a = *(const float4*)(bwd + idx + B_ * E_);
        v.x += a.x; v.y += a.y; v.z += a.z; v.w += a.w;
    }
    *(float4*)(g_qin + idx) = v;
}

// ---------------- proj_q: g_q = qin @ Wq^T + bq -> (b,h,t,d) ----------------
__global__ __launch_bounds__(256, 2) void proj_q_kernel(const float* __restrict__ W,
                                                        const float* __restrict__ bias) {
    __shared__ float Ah[128][LDK], Al[128][LDK], Bh[128][LDK], Bl[128][LDK];
    const int row0 = blockIdx.y * 128;
    const int col0 = blockIdx.x * 128;
    const float* A = g_qin + (size_t)row0 * E_;
    const float* Bw = W + (size_t)col0 * E_;
    float acc[4][4][4] = {};
    for (int k0 = 0; k0 < E_; k0 += 16) {
        stage3(A + k0, E_, Ah, Al);
        stage3(Bw + k0, E_, Bh, Bl);
        __syncthreads();
        mma_block3(Ah, Al, Bh, Bl, acc);
        __syncthreads();
    }
    const int lane = threadIdx.x & 31, warp = threadIdx.x >> 5;
    const int wm = warp >> 2, wn = warp & 3;
    const int gid = lane >> 2, t4 = lane & 3;
    #pragma unroll
    for (int mi = 0; mi < 4; mi++) {
        #pragma unroll
        for (int ni = 0; ni < 4; ni++) {
            int r = row0 + wm * 64 + mi * 16 + gid;
            int f = col0 + wn * 32 + ni * 8 + 2 * t4;
            int h = f >> 6, d = f & 63;
            float bb0 = bias[f], bb1 = bias[f + 1];
            int t = r >> 3, b = r & 7;
            *(float2*)&g_q[(size_t)(((b << 3) + h) * T_ + t) * D_ + d] =
                make_float2(acc[mi][ni][0] + bb0, acc[mi][ni][1] + bb1);
            *(float2*)&g_q[(size_t)(((b << 3) + h) * T_ + t + 1) * D_ + d] =
                make_float2(acc[mi][ni][2] + bb0, acc[mi][ni][3] + bb1);
        }
    }
}

// ---------------- proj_kv -> g_k / g_v (b,h,s,d) ----------------
__global__ __launch_bounds__(256, 2) void proj_kv_kernel(const float* __restrict__ fwd,
                                                         const float* __restrict__ bwd,
                                                         const float* __restrict__ W,
                                                         const float* __restrict__ bias) {
    __shared__ float Ah[128][LDK], Al[128][LDK], Bh[128][LDK], Bl[128][LDK];
    const int row0 = blockIdx.y * 128;   // kv_in rows (s*B+b)
    const int col0 = blockIdx.x * 128;   // f in [0,1024)
    const float* A = (row0 < T_ * B_) ? (fwd + (size_t)row0 * E_)
                                      : (bwd + (size_t)(row0 - T_ * B_) * E_);
    const float* Bw = W + (size_t)(E_ + col0) * E_;
    float acc[4][4][4] = {};
    for (int k0 = 0; k0 < E_; k0 += 16) {
        stage3(A + k0, E_, Ah, Al);
        stage3(Bw + k0, E_, Bh, Bl);
        __syncthreads();
        mma_block3(Ah, Al, Bh, Bl, acc);
        __syncthreads();
    }
    const int lane = threadIdx.x & 31, warp = threadIdx.x >> 5;
    const int wm = warp >> 2, wn = warp & 3;
    const int gid = lane >> 2, t4 = lane & 3;
    float* dstbase = (col0 < E_) ? g_k : g_v;
    #pragma unroll
    for (int mi = 0; mi < 4; mi++) {
        #pragma unroll
        for (int ni = 0; ni < 4; ni++) {
            int r = row0 + wm * 64 + mi * 16 + gid;
            int f = col0 + wn * 32 + ni * 8 + 2 * t4;
            float bb0 = bias[E_ + f], bb1 = bias[E_ + f + 1];
            int f2 = f & (E_ - 1);
            int h = f2 >> 6, d = f2 & 63;
            int s = r >> 3, b = r & 7;
            *(float2*)&dstbase[((size_t)((b << 3) + h) * S_ + s) * D_ + d] =
                make_float2(acc[mi][ni][0] + bb0, acc[mi][ni][1] + bb1);
            *(float2*)&dstbase[((size_t)((b << 3) + h) * S_ + s + 1) * D_ + d] =
                make_float2(acc[mi][ni][2] + bb0, acc[mi][ni][3] + bb1);
        }
    }
}

// ---------------- scores: raw q.k (3xTF32); compacted grid (9 active s-tiles) ----------------
__global__ __launch_bounds__(256, 2) void scores_kernel() {
    const int bh = blockIdx.z;
    const int it = blockIdx.y;           // t-tile 0..7
    const int n = blockIdx.x;            // 0..8 active s-tile index
    const int j = (n <= it) ? n : n + 7; // skip tiles it+1..it+7
    const int t0 = it * 128;
    const int s0 = j * 128;
    __shared__ float Ah[128][LDK], Al[128][LDK], Bh[128][LDK], Bl[128][LDK];
    const float* Q = g_q + (size_t)bh * T_ * D_ + (size_t)t0 * D_;
    const float* K = g_k + (size_t)bh * S_ * D_ + (size_t)s0 * D_;
    float acc[4][4][4] = {};
    for (int k0 = 0; k0 < D_; k0 += 16) {
        stage3(Q + k0, D_, Ah, Al);
        stage3(K + k0, D_, Bh, Bl);
        __syncthreads();
        mma_block3(Ah, Al, Bh, Bl, acc);
        __syncthreads();
    }
    float* P = g_p + (size_t)bh * T_ * S_;
    const int lane = threadIdx.x & 31, warp = threadIdx.x >> 5;
    const int wm = warp >> 2, wn = warp & 3;
    const int gid = lane >> 2, t4 = lane & 3;
    #pragma unroll
    for (int mi = 0; mi < 4; mi++) {
        #pragma unroll
        for (int ni = 0; ni < 4; ni++) {
            int r = t0 + wm * 64 + mi * 16 + gid;
            int c = s0 + wn * 32 + ni * 8 + 2 * t4;
            *(float2*)&P[(size_t)r * S_ + c] = make_float2(acc[mi][ni][0], acc[mi][ni][1]);
            *(float2*)&P[(size_t)(r + 8) * S_ + c] = make_float2(acc[mi][ni][2], acc[mi][ni][3]);
        }
    }
}

// ---------------- softmax per (b,t) over heads + head-mean (float4, band-skip) ----------------
__device__ __forceinline__ float blk_reduce(float v, bool is_max, float* red) {
    #pragma unroll
    for (int o = 16; o; o >>= 1) {
        float w = __shfl_xor_sync(0xffffffffu, v, o);
        v = is_max ? fmaxf(v, w) : v + w;
    }
    if ((threadIdx.x & 31) == 0) red[threadIdx.x >> 5] = v;
    __syncthreads();
    if (threadIdx.x < 32) {
        float x = (threadIdx.x < 8) ? red[threadIdx.x] : (is_max ? -1e30f : 0.f);
        #pragma unroll
        for (int o = 4; o; o >>= 1) {
            float w = __shfl_xor_sync(0xffffffffu, x, o);
            x = is_max ? fmaxf(x, w) : x + w;
        }
        if (threadIdx.x == 0) red[0] = x;
    }
    __syncthreads();
    float r = red[0];
    __syncthreads();
    return r;
}

__global__ void softmax_avg_kernel(const int* __restrict__ kpm,
                                   float* __restrict__ avg_out) {
    __shared__ float red[32];
    const int bt = blockIdx.x;
    const int b = bt >> 10;
    const int t = bt & (T_ - 1);
    const int t0 = t & ~127;             // t-tile start (attn read granularity)
    const int tid = threadIdx.x;
    // each thread owns 2 float4 chunks: s4 = tid*4 + i*1024
    bool msk[2][4];
    bool wr[2];
    #pragma unroll
    for (int i = 0; i < 2; i++) {
        int s4 = (tid << 2) + (i << 10);
        wr[i] = (s4 < t0 + 128) || (s4 >= t0 + 1024);  // attn reads this chunk
        #pragma unroll
        for (int e = 0; e < 4; e++) {
            int s = s4 + e;
            msk[i][e] = (s >= t && s <= t + T_) || (kpm[b * T_ + (s & (T_ - 1))] != 0);
        }
    }
    float avg[2][4] = {};
    for (int h = 0; h < H_; h++) {
        float* row = g_p + ((size_t)(((b << 3) + h) * T_ + t)) * S_;
        float vreg[2][4];
        float m = -1e30f;
        #pragma unroll
        for (int i = 0; i < 2; i++) {
            int s4 = (tid << 2) + (i << 10);
            float4 v = *(const float4*)(row + s4);
            float tmp[4] = {v.x, v.y, v.z, v.w};
            #pragma unroll
            for (int e = 0; e < 4; e++) {
                float x = msk[i][e] ? -1e30f : tmp[e];
                vreg[i][e] = x;
                m = fmaxf(m, x);
            }
        }
        m = blk_reduce(m, true, red);
        float sum = 0.f;
        #pragma unroll
        for (int i = 0; i < 2; i++)
            #pragma unroll
            for (int e = 0; e < 4; e++) {
                if (!msk[i][e]) { vreg[i][e] = __expf(vreg[i][e] - m); sum += vreg[i][e]; }
                else vreg[i][e] = 0.f;
            }
        sum = blk_reduce(sum, false, red);
        float inv = 1.f / sum;
        #pragma unroll
        for (int i = 0; i < 2; i++) {
            int s4 = (tid << 2) + (i << 10);
            float p0 = vreg[i][0] * inv, p1 = vreg[i][1] * inv;
            float p2 = vreg[i][2] * inv, p3 = vreg[i][3] * inv;
            if (wr[i])
                *(float4*)(row + s4) = make_float4(p0, p1, p2, p3);
            avg[i][0] += p0; avg[i][1] += p1; avg[i][2] += p2; avg[i][3] += p3;
        }
    }
    size_t o = (size_t)bt * S_;
    #pragma unroll
    for (int i = 0; i < 2; i++) {
        int s4 = (tid << 2) + (i << 10);
        *(float4*)(avg_out + o + s4) = make_float4(avg[i][0] * 0.125f, avg[i][1] * 0.125f,
                                                   avg[i][2] * 0.125f, avg[i][3] * 0.125f);
    }
}

// ---------------- attn = p @ v (1-pass tf32, BM=128 BN=64, skip zero tiles) ----------------
__global__ __launch_bounds__(256, 2) void attn_kernel() {
    __shared__ float Ph[128][LDK];
    __shared__ float Vh[16][LDV];
    const int t0 = blockIdx.x * 128;
    const int bh = blockIdx.y;
    const float* P = g_p + (size_t)bh * T_ * S_ + (size_t)t0 * S_;
    const float* V = g_v + (size_t)bh * S_ * D_;
    const int tid = threadIdx.x;
    const int lane = tid & 31, warp = tid >> 5;
    const int wm = warp >> 1, wn = warp & 1;   // warp tile: 32(t) x 32(d)
    const int gid = lane >> 2, t4 = lane & 3;
    float acc[2][4][4] = {};
    for (int k0 = 0; k0 < S_; k0 += 16) {
        if (k0 >= t0 + 128 && k0 + 15 <= t0 + T_) continue;  // p exactly 0 here
        stage1(P + k0, S_, Ph);
        {   // stage V 16x64 -> Vh[k][n]
            int r = tid >> 4, c = (tid & 15) << 2;
            float4 v = *(const float4*)(V + (size_t)(k0 + r) * D_ + c);
            float4 hv = make_float4(__uint_as_float(f2tf32(v.x)), __uint_as_float(f2tf32(v.y)),
                                    __uint_as_float(f2tf32(v.z)), __uint_as_float(f2tf32(v.w)));
            *(float4*)&Vh[r][c] = hv;
        }
        __syncthreads();
        #pragma unroll
        for (int kk = 0; kk < 16; kk += 8) {
            uint32_t ah[2][4];
            #pragma unroll
            for (int mi = 0; mi < 2; mi++) {
                int r = wm * 32 + mi * 16 + gid;
                ah[mi][0] = __float_as_uint(Ph[r][kk + t4]);
                ah[mi][1] = __float_as_uint(Ph[r + 8][kk + t4]);
                ah[mi][2] = __float_as_uint(Ph[r][kk + t4 + 4]);
                ah[mi][3] = __float_as_uint(Ph[r + 8][kk + t4 + 4]);
            }
            #pragma unroll
            for (int ni = 0; ni < 4; ni++) {
                int c = wn * 32 + ni * 8 + gid;
                uint32_t b0 = __float_as_uint(Vh[kk + t4][c]);
                uint32_t b1 = __float_as_uint(Vh[kk + t4 + 4][c]);
                #pragma unroll
                for (int mi = 0; mi < 2; mi++)
                    mma8(acc[mi][ni], ah[mi][0], ah[mi][1], ah[mi][2], ah[mi][3], b0, b1);
            }
        }
        __syncthreads();
    }
    const int b = bh >> 3, h = bh & 7;
    #pragma unroll
    for (int mi = 0; mi < 2; mi++) {
        #pragma unroll
        for (int ni = 0; ni < 4; ni++) {
            int t = t0 + wm * 32 + mi * 16 + gid;
            int d = wn * 32 + ni * 8 + 2 * t4;
            *(float2*)&g_attn[(size_t)((t << 3) + b) * E_ + (h << 6) + d] =
                make_float2(acc[mi][ni][0], acc[mi][ni][1]);
            *(float2*)&g_attn[(size_t)(((t + 8) << 3) + b) * E_ + (h << 6) + d] =
                make_float2(acc[mi][ni][2], acc[mi][ni][3]);
        }
    }
}

// ---------------- out = attn @ out_w^T + out_b (1-pass tf32) ----------------
__global__ __launch_bounds__(256, 2) void out_proj_kernel(const float* __restrict__ W,
                                                          const float* __restrict__ bias,
                                                          float* __restrict__ out) {
    __shared__ float Ah[128][LDK], Bh[128][LDK];
    const int row0 = blockIdx.y * 128;
    const int col0 = blockIdx.x * 128;
    const float* A = g_attn + (size_t)row0 * E_;
    const float* Bw = W + (size_t)col0 * E_;
    float acc[4][4][4] = {};
    for (int k0 = 0; k0 < E_; k0 += 16) {
        stage1(A + k0, E_, Ah);
        stage1(Bw + k0, E_, Bh);
        __syncthreads();
        mma_block1(Ah, Bh, acc);
        __syncthreads();
    }
    const int lane = threadIdx.x & 31, warp = threadIdx.x >> 5;
    const int wm = warp >> 2, wn = warp & 3;
    const int gid = lane >> 2, t4 = lane & 3;
    #pragma unroll
    for (int mi = 0; mi < 4; mi++) {
        #pragma unroll
        for (int ni = 0; ni < 4; ni++) {
            int r = row0 + wm * 64 + mi * 16 + gid;
            int f = col0 + wn * 32 + ni * 8 + 2 * t4;
            float bb0 = bias[f], bb1 = bias[f + 1];
            *(float2*)&out[(size_t)r * E_ + f] =
                make_float2(acc[mi][ni][0] + bb0, acc[mi][ni][1] + bb1);
            *(float2*)&out[(size_t)(r + 8) * E_ + f] =
                make_float2(acc[mi][ni][2] + bb0, acc[mi][ni][3] + bb1);
        }
    }
}

// ---------------- launch ----------------
extern "C" void kernel_launch(void* const* d_in, const int* in_sizes, int n_in,
                              void* d_out, int out_size) {
    const float* fwd  = (const float*)d_in[0];
    const float* bwd  = (const float*)d_in[1];
    const int*   kpm  = (const int*)d_in[2];
    const float* W    = (const float*)d_in[3];   // (3E, E)
    const float* bias = (const float*)d_in[4];   // (3E,)
    const float* outw = (const float*)d_in[5];   // (E, E)
    const float* outb = (const float*)d_in[6];   // (E,)
    float* out = (float*)d_out;                       // (T,B,E)
    float* avg = out + (size_t)T_ * B_ * E_;          // (B,T,S)

    build_qin_kernel<<<(T_ * B_ * E_) / 1024, 256>>>(fwd, bwd);
    proj_q_kernel<<<dim3(E_ / 128, (T_ * B_) / 128), 256>>>(W, bias);
    proj_kv_kernel<<<dim3((2 * E_) / 128, (S_ * B_) / 128), 256>>>(fwd, bwd, W, bias);
    scores_kernel<<<dim3(9, T_ / 128, B_ * H_), 256>>>();
    softmax_avg_kernel<<<B_ * T_, 256>>>(kpm, avg);
    attn_kernel<<<dim3(T_ / 128, B_ * H_), 256>>>();
    out_proj_kernel<<<dim3(E_ / 128, (T_ * B_) / 128), 256>>>(outw, outb, out);
}

// round 13
// speedup vs baseline: 1.2319x; 1.2319x over previous
#include <cuda_runtime.h>
#include <cuda_bf16.h>
#include <math.h>
#include <stdint.h>

#define T_ 1024
#define B_ 8
#define E_ 512
#define H_ 8
#define D_ 64
#define S_ 2048
#define LDA 24
#define LDVB 72

// ---------------- scratch (device globals; no allocations) ----------------
__device__ float g_qin[T_ * B_ * E_];                 // (t,b,e)
__device__ float g_q[B_ * H_ * T_ * D_];              // (b,h,t,d)
__device__ float g_k[B_ * H_ * S_ * D_];              // (b,h,s,d)
__device__ float g_v[B_ * H_ * S_ * D_];              // (b,h,s,d)
__device__ float g_p[(size_t)B_ * H_ * T_ * S_];      // (b,h,t,s)
__device__ float g_attn[T_ * B_ * E_];                // (t,b, h*64+d)

// ---------------- bf16 split + mma helpers ----------------
__device__ __forceinline__ void mma16(float c[4], const uint32_t a[4],
                                      uint32_t b0, uint32_t b1) {
    asm volatile(
        "mma.sync.aligned.m16n8k16.row.col.f32.bf16.bf16.f32 "
        "{%0,%1,%2,%3},{%4,%5,%6,%7},{%8,%9},{%0,%1,%2,%3};"
        : "+f"(c[0]), "+f"(c[1]), "+f"(c[2]), "+f"(c[3])
        : "r"(a[0]), "r"(a[1]), "r"(a[2]), "r"(a[3]), "r"(b0), "r"(b1));
}

// A fragment (m16 x k16) from [m][k] rows, non-trans x4
__device__ __forceinline__ void lda_frag(uint32_t f[4],
                                         const __nv_bfloat16 (*M)[LDA], int rbase) {
    int lane = threadIdx.x & 31;
    int lm = lane & 7, sel = lane >> 3;
    int row = rbase + lm + (sel & 1) * 8;
    int col = (sel >> 1) * 8;
    uint32_t addr = (uint32_t)__cvta_generic_to_shared(&M[row][col]);
    asm volatile("ldmatrix.sync.aligned.m8n8.x4.shared.b16 {%0,%1,%2,%3}, [%4];"
                 : "=r"(f[0]), "=r"(f[1]), "=r"(f[2]), "=r"(f[3]) : "r"(addr));
}

// B fragments for an ni-PAIR (n16 x k16) from [n][k] rows, non-trans x4
// f = {b0(ni_even), b1(ni_even), b0(ni_odd), b1(ni_odd)}
__device__ __forceinline__ void ldb_frag(uint32_t f[4],
                                         const __nv_bfloat16 (*M)[LDA], int nbase) {
    int lane = threadIdx.x & 31;
    int lm = lane & 7, sel = lane >> 3;
    int row = nbase + lm + (sel >> 1) * 8;
    int col = (sel & 1) * 8;
    uint32_t addr = (uint32_t)__cvta_generic_to_shared(&M[row][col]);
    asm volatile("ldmatrix.sync.aligned.m8n8.x4.shared.b16 {%0,%1,%2,%3}, [%4];"
                 : "=r"(f[0]), "=r"(f[1]), "=r"(f[2]), "=r"(f[3]) : "r"(addr));
}

// B fragments for an ni-pair from V stored [k][n] (natural), via .trans
__device__ __forceinline__ void ldvb_frag(uint32_t f[4],
                                          const __nv_bfloat16 (*M)[LDVB], int nbase) {
    int lane = threadIdx.x & 31;
    int lm = lane & 7, sel = lane >> 3;
    int row = lm + (sel & 1) * 8;          // k
    int col = nbase + (sel >> 1) * 8;      // n
    uint32_t addr = (uint32_t)__cvta_generic_to_shared(&M[row][col]);
    asm volatile("ldmatrix.sync.aligned.m8n8.x4.trans.shared.b16 {%0,%1,%2,%3}, [%4];"
                 : "=r"(f[0]), "=r"(f[1]), "=r"(f[2]), "=r"(f[3]) : "r"(addr));
}

// stage 128 rows x 16 cols fp32 -> bf16 hi/lo planes
__device__ __forceinline__ void stage_bf(const float* __restrict__ src, int ld,
                                         __nv_bfloat16 (*dh)[LDA],
                                         __nv_bfloat16 (*dl)[LDA]) {
    int r = threadIdx.x >> 1, c = (threadIdx.x & 1) << 3;
    const float* p = src + (size_t)r * ld + c;
    float4 v0 = *(const float4*)p;
    float4 v1 = *(const float4*)(p + 4);
    float v[8] = {v0.x, v0.y, v0.z, v0.w, v1.x, v1.y, v1.z, v1.w};
    uint32_t hu[4], lu[4];
    #pragma unroll
    for (int i = 0; i < 4; i++) {
        __nv_bfloat16 h0 = __float2bfloat16(v[2*i]);
        __nv_bfloat16 l0 = __float2bfloat16(v[2*i] - __bfloat162float(h0));
        __nv_bfloat16 h1 = __float2bfloat16(v[2*i+1]);
        __nv_bfloat16 l1 = __float2bfloat16(v[2*i+1] - __bfloat162float(h1));
        hu[i] = (uint32_t)__bfloat16_as_ushort(h0) | ((uint32_t)__bfloat16_as_ushort(h1) << 16);
        lu[i] = (uint32_t)__bfloat16_as_ushort(l0) | ((uint32_t)__bfloat16_as_ushort(l1) << 16);
    }
    *(uint4*)&dh[r][c] = make_uint4(hu[0], hu[1], hu[2], hu[3]);
    *(uint4*)&dl[r][c] = make_uint4(lu[0], lu[1], lu[2], lu[3]);
}

// 128x128 block, 3-pass bf16, one k16 slab already staged
__device__ __forceinline__ void mma_slab3(const __nv_bfloat16 (*Ah)[LDA],
                                          const __nv_bfloat16 (*Al)[LDA],
                                          const __nv_bfloat16 (*Bh)[LDA],
                                          const __nv_bfloat16 (*Bl)[LDA],
                                          float acc[4][4][4]) {
    const int warp = threadIdx.x >> 5;
    const int wm = warp >> 2, wn = warp & 3;
    uint32_t ah[4][4], al[4][4], bh[2][4], bl[2][4];
    #pragma unroll
    for (int mi = 0; mi < 4; mi++) {
        lda_frag(ah[mi], Ah, wm * 64 + mi * 16);
        lda_frag(al[mi], Al, wm * 64 + mi * 16);
    }
    #pragma unroll
    for (int np = 0; np < 2; np++) {
        ldb_frag(bh[np], Bh, wn * 32 + np * 16);
        ldb_frag(bl[np], Bl, wn * 32 + np * 16);
    }
    #pragma unroll
    for (int mi = 0; mi < 4; mi++) {
        #pragma unroll
        for (int ni = 0; ni < 4; ni++) {
            int np = ni >> 1, o = (ni & 1) << 1;
            mma16(acc[mi][ni], ah[mi], bh[np][o], bh[np][o + 1]);
            mma16(acc[mi][ni], ah[mi], bl[np][o], bl[np][o + 1]);
            mma16(acc[mi][ni], al[mi], bh[np][o], bh[np][o + 1]);
        }
    }
}

// ---------------- q_in = shift(fwd,+1) + shift(bwd,-1), float4 ----------------
__global__ void build_qin_kernel(const float* __restrict__ fwd,
                                 const float* __restrict__ bwd) {
    int i4 = blockIdx.x * blockDim.x + threadIdx.x;
    int idx = i4 << 2;
    int t = idx / (B_ * E_);
    float4 v = make_float4(0.f, 0.f, 0.f, 0.f);
    if (t > 0) {
        float4 a = *(const float4*)(fwd + idx - B_ * E_);
        v.x += a.x; v.y += a.y; v.z += a.z; v.w += a.w;
    }
    if (t < T_ - 1) {
        float4 a = *(const float4*)(bwd + idx + B_ * E_);
        v.x += a.x; v.y += a.y; v.z += a.z; v.w += a.w;
    }
    *(float4*)(g_qin + idx) = v;
}

// ---------------- proj_q ----------------
__global__ __launch_bounds__(256, 2) void proj_q_kernel(const float* __restrict__ W,
                                                        const float* __restrict__ bias) {
    __shared__ __nv_bfloat16 Ah[128][LDA], Al[128][LDA], Bh[128][LDA], Bl[128][LDA];
    const int row0 = blockIdx.y * 128;
    const int col0 = blockIdx.x * 128;
    const float* A = g_qin + (size_t)row0 * E_;
    const float* Bw = W + (size_t)col0 * E_;
    float acc[4][4][4] = {};
    for (int k0 = 0; k0 < E_; k0 += 16) {
        stage_bf(A + k0, E_, Ah, Al);
        stage_bf(Bw + k0, E_, Bh, Bl);
        __syncthreads();
        mma_slab3(Ah, Al, Bh, Bl, acc);
        __syncthreads();
    }
    const int lane = threadIdx.x & 31, warp = threadIdx.x >> 5;
    const int wm = warp >> 2, wn = warp & 3;
    const int gid = lane >> 2, t4 = lane & 3;
    #pragma unroll
    for (int mi = 0; mi < 4; mi++) {
        #pragma unroll
        for (int ni = 0; ni < 4; ni++) {
            int r = row0 + wm * 64 + mi * 16 + gid;
            int f = col0 + wn * 32 + ni * 8 + 2 * t4;
            int h = f >> 6, d = f & 63;
            float bb0 = bias[f], bb1 = bias[f + 1];
            int t = r >> 3, b = r & 7;
            *(float2*)&g_q[(size_t)(((b << 3) + h) * T_ + t) * D_ + d] =
                make_float2(acc[mi][ni][0] + bb0, acc[mi][ni][1] + bb1);
            *(float2*)&g_q[(size_t)(((b << 3) + h) * T_ + t + 1) * D_ + d] =
                make_float2(acc[mi][ni][2] + bb0, acc[mi][ni][3] + bb1);
        }
    }
}

// ---------------- proj_kv ----------------
__global__ __launch_bounds__(256, 2) void proj_kv_kernel(const float* __restrict__ fwd,
                                                         const float* __restrict__ bwd,
                                                         const float* __restrict__ W,
                                                         const float* __restrict__ bias) {
    __shared__ __nv_bfloat16 Ah[128][LDA], Al[128][LDA], Bh[128][LDA], Bl[128][LDA];
    const int row0 = blockIdx.y * 128;
    const int col0 = blockIdx.x * 128;
    const float* A = (row0 < T_ * B_) ? (fwd + (size_t)row0 * E_)
                                      : (bwd + (size_t)(row0 - T_ * B_) * E_);
    const float* Bw = W + (size_t)(E_ + col0) * E_;
    float acc[4][4][4] = {};
    for (int k0 = 0; k0 < E_; k0 += 16) {
        stage_bf(A + k0, E_, Ah, Al);
        stage_bf(Bw + k0, E_, Bh, Bl);
        __syncthreads();
        mma_slab3(Ah, Al, Bh, Bl, acc);
        __syncthreads();
    }
    const int lane = threadIdx.x & 31, warp = threadIdx.x >> 5;
    const int wm = warp >> 2, wn = warp & 3;
    const int gid = lane >> 2, t4 = lane & 3;
    float* dstbase = (col0 < E_) ? g_k : g_v;
    #pragma unroll
    for (int mi = 0; mi < 4; mi++) {
        #pragma unroll
        for (int ni = 0; ni < 4; ni++) {
            int r = row0 + wm * 64 + mi * 16 + gid;
            int f = col0 + wn * 32 + ni * 8 + 2 * t4;
            float bb0 = bias[E_ + f], bb1 = bias[E_ + f + 1];
            int f2 = f & (E_ - 1);
            int h = f2 >> 6, d = f2 & 63;
            int s = r >> 3, b = r & 7;
            *(float2*)&dstbase[((size_t)((b << 3) + h) * S_ + s) * D_ + d] =
                make_float2(acc[mi][ni][0] + bb0, acc[mi][ni][1] + bb1);
            *(float2*)&dstbase[((size_t)((b << 3) + h) * S_ + s + 1) * D_ + d] =
                make_float2(acc[mi][ni][2] + bb0, acc[mi][ni][3] + bb1);
        }
    }
}

// ---------------- scores: raw q.k, compacted grid ----------------
__global__ __launch_bounds__(256, 2) void scores_kernel() {
    const int bh = blockIdx.z;
    const int it = blockIdx.y;
    const int n = blockIdx.x;
    const int j = (n <= it) ? n : n + 7;
    const int t0 = it * 128;
    const int s0 = j * 128;
    __shared__ __nv_bfloat16 Ah[128][LDA], Al[128][LDA], Bh[128][LDA], Bl[128][LDA];
    const float* Q = g_q + (size_t)bh * T_ * D_ + (size_t)t0 * D_;
    const float* K = g_k + (size_t)bh * S_ * D_ + (size_t)s0 * D_;
    float acc[4][4][4] = {};
    for (int k0 = 0; k0 < D_; k0 += 16) {
        stage_bf(Q + k0, D_, Ah, Al);
        stage_bf(K + k0, D_, Bh, Bl);
        __syncthreads();
        mma_slab3(Ah, Al, Bh, Bl, acc);
        __syncthreads();
    }
    float* P = g_p + (size_t)bh * T_ * S_;
    const int lane = threadIdx.x & 31, warp = threadIdx.x >> 5;
    const int wm = warp >> 2, wn = warp & 3;
    const int gid = lane >> 2, t4 = lane & 3;
    #pragma unroll
    for (int mi = 0; mi < 4; mi++) {
        #pragma unroll
        for (int ni = 0; ni < 4; ni++) {
            int r = t0 + wm * 64 + mi * 16 + gid;
            int c = s0 + wn * 32 + ni * 8 + 2 * t4;
            *(float2*)&P[(size_t)r * S_ + c] = make_float2(acc[mi][ni][0], acc[mi][ni][1]);
            *(float2*)&P[(size_t)(r + 8) * S_ + c] = make_float2(acc[mi][ni][2], acc[mi][ni][3]);
        }
    }
}

// ---------------- softmax per (b,t) + head-mean; band-skip both ways ----------------
__device__ __forceinline__ float blk_reduce(float v, bool is_max, float* red) {
    #pragma unroll
    for (int o = 16; o; o >>= 1) {
        float w = __shfl_xor_sync(0xffffffffu, v, o);
        v = is_max ? fmaxf(v, w) : v + w;
    }
    if ((threadIdx.x & 31) == 0) red[threadIdx.x >> 5] = v;
    __syncthreads();
    if (threadIdx.x < 32) {
        float x = (threadIdx.x < 8) ? red[threadIdx.x] : (is_max ? -1e30f : 0.f);
        #pragma unroll
        for (int o = 4; o; o >>= 1) {
            float w = __shfl_xor_sync(0xffffffffu, x, o);
            x = is_max ? fmaxf(x, w) : x + w;
        }
        if (threadIdx.x == 0) red[0] = x;
    }
    __syncthreads();
    float r = red[0];
    __syncthreads();
    return r;
}

__global__ void softmax_avg_kernel(const int* __restrict__ kpm,
                                   float* __restrict__ avg_out) {
    __shared__ float red[32];
    const int bt = blockIdx.x;
    const int b = bt >> 10;
    const int t = bt & (T_ - 1);
    const int t0 = t & ~127;
    const int tid = threadIdx.x;
    bool msk[2][4];
    bool wr[2], band[2];
    #pragma unroll
    for (int i = 0; i < 2; i++) {
        int s4 = (tid << 2) + (i << 10);
        wr[i] = (s4 < t0 + 128) || (s4 >= t0 + 1024);       // attn reads this chunk
        band[i] = (s4 >= t) && (s4 + 3 <= t + T_);           // fully masked -> skip load
        #pragma unroll
        for (int e = 0; e < 4; e++) {
            int s = s4 + e;
            msk[i][e] = (s >= t && s <= t + T_) || (kpm[b * T_ + (s & (T_ - 1))] != 0);
        }
    }
    float avg[2][4] = {};
    for (int h = 0; h < H_; h++) {
        float* row = g_p + ((size_t)(((b << 3) + h) * T_ + t)) * S_;
        float vreg[2][4];
        float m = -1e30f;
        #pragma unroll
        for (int i = 0; i < 2; i++) {
            int s4 = (tid << 2) + (i << 10);
            float4 v = band[i] ? make_float4(0.f, 0.f, 0.f, 0.f)
                               : *(const float4*)(row + s4);
            float tmp[4] = {v.x, v.y, v.z, v.w};
            #pragma unroll
            for (int e = 0; e < 4; e++) {
                float x = msk[i][e] ? -1e30f : tmp[e];
                vreg[i][e] = x;
                m = fmaxf(m, x);
            }
        }
        m = blk_reduce(m, true, red);
        float sum = 0.f;
        #pragma unroll
        for (int i = 0; i < 2; i++)
            #pragma unroll
            for (int e = 0; e < 4; e++) {
                if (!msk[i][e]) { vreg[i][e] = __expf(vreg[i][e] - m); sum += vreg[i][e]; }
                else vreg[i][e] = 0.f;
            }
        sum = blk_reduce(sum, false, red);
        float inv = 1.f / sum;
        #pragma unroll
        for (int i = 0; i < 2; i++) {
            int s4 = (tid << 2) + (i << 10);
            float p0 = vreg[i][0] * inv, p1 = vreg[i][1] * inv;
            float p2 = vreg[i][2] * inv, p3 = vreg[i][3] * inv;
            if (wr[i])
                *(float4*)(row + s4) = make_float4(p0, p1, p2, p3);
            avg[i][0] += p0; avg[i][1] += p1; avg[i][2] += p2; avg[i][3] += p3;
        }
    }
    size_t o = (size_t)bt * S_;
    #pragma unroll
    for (int i = 0; i < 2; i++) {
        int s4 = (tid << 2) + (i << 10);
        *(float4*)(avg_out + o + s4) = make_float4(avg[i][0] * 0.125f, avg[i][1] * 0.125f,
                                                   avg[i][2] * 0.125f, avg[i][3] * 0.125f);
    }
}

// ---------------- attn = p @ v (3-pass bf16, skip zero k-tiles) ----------------
__global__ __launch_bounds__(256, 2) void attn_kernel() {
    __shared__ __nv_bfloat16 Ph[128][LDA], Pl[128][LDA];
    __shared__ __nv_bfloat16 Vh[16][LDVB], Vl[16][LDVB];
    const int t0 = blockIdx.x * 128;
    const int bh = blockIdx.y;
    const float* P = g_p + (size_t)bh * T_ * S_ + (size_t)t0 * S_;
    const float* V = g_v + (size_t)bh * S_ * D_;
    const int tid = threadIdx.x;
    const int lane = tid & 31, warp = tid >> 5;
    const int wm = warp >> 1, wn = warp & 1;   // warp tile: 32(t) x 32(d)
    const int gid = lane >> 2, t4 = lane & 3;
    float acc[2][4][4] = {};
    for (int k0 = 0; k0 < S_; k0 += 16) {
        if (k0 >= t0 + 128 && k0 + 15 <= t0 + T_) continue;  // p exactly 0 here
        stage_bf(P + k0, S_, Ph, Pl);
        {   // stage V 16x64 natural [s][d]
            int r = tid >> 4, c = (tid & 15) << 2;
            float4 v = *(const float4*)(V + (size_t)(k0 + r) * D_ + c);
            float vv[4] = {v.x, v.y, v.z, v.w};
            uint32_t hu[2], lu[2];
            #pragma unroll
            for (int i = 0; i < 2; i++) {
                __nv_bfloat16 h0 = __float2bfloat16(vv[2*i]);
                __nv_bfloat16 l0 = __float2bfloat16(vv[2*i] - __bfloat162float(h0));
                __nv_bfloat16 h1 = __float2bfloat16(vv[2*i+1]);
                __nv_bfloat16 l1 = __float2bfloat16(vv[2*i+1] - __bfloat162float(h1));
                hu[i] = (uint32_t)__bfloat16_as_ushort(h0) | ((uint32_t)__bfloat16_as_ushort(h1) << 16);
                lu[i] = (uint32_t)__bfloat16_as_ushort(l0) | ((uint32_t)__bfloat16_as_ushort(l1) << 16);
            }
            *(uint2*)&Vh[r][c] = make_uint2(hu[0], hu[1]);
            *(uint2*)&Vl[r][c] = make_uint2(lu[0], lu[1]);
        }
        __syncthreads();
        uint32_t ah[2][4], al[2][4], bh2[2][4], bl2[2][4];
        #pragma unroll
        for (int mi = 0; mi < 2; mi++) {
            lda_frag(ah[mi], Ph, wm * 32 + mi * 16);
            lda_frag(al[mi], Pl, wm * 32 + mi * 16);
        }
        #pragma unroll
        for (int np = 0; np < 2; np++) {
            ldvb_frag(bh2[np], Vh, wn * 32 + np * 16);
            ldvb_frag(bl2[np], Vl, wn * 32 + np * 16);
        }
        #pragma unroll
        for (int mi = 0; mi < 2; mi++) {
            #pragma unroll
            for (int ni = 0; ni < 4; ni++) {
                int np = ni >> 1, o = (ni & 1) << 1;
                mma16(acc[mi][ni], ah[mi], bh2[np][o], bh2[np][o + 1]);
                mma16(acc[mi][ni], ah[mi], bl2[np][o], bl2[np][o + 1]);
                mma16(acc[mi][ni], al[mi], bh2[np][o], bh2[np][o + 1]);
            }
        }
        __syncthreads();
    }
    const int b = bh >> 3, h = bh & 7;
    #pragma unroll
    for (int mi = 0; mi < 2; mi++) {
        #pragma unroll
        for (int ni = 0; ni < 4; ni++) {
            int t = t0 + wm * 32 + mi * 16 + gid;
            int d = wn * 32 + ni * 8 + 2 * t4;
            *(float2*)&g_attn[(size_t)((t << 3) + b) * E_ + (h << 6) + d] =
                make_float2(acc[mi][ni][0], acc[mi][ni][1]);
            *(float2*)&g_attn[(size_t)(((t + 8) << 3) + b) * E_ + (h << 6) + d] =
                make_float2(acc[mi][ni][2], acc[mi][ni][3]);
        }
    }
}

// ---------------- out = attn @ out_w^T + out_b (3-pass bf16) ----------------
__global__ __launch_bounds__(256, 2) void out_proj_kernel(const float* __restrict__ W,
                                                          const float* __restrict__ bias,
                                                          float* __restrict__ out) {
    __shared__ __nv_bfloat16 Ah[128][LDA], Al[128][LDA], Bh[128][LDA], Bl[128][LDA];
    const int row0 = blockIdx.y * 128;
    const int col0 = blockIdx.x * 128;
    const float* A = g_attn + (size_t)row0 * E_;
    const float* Bw = W + (size_t)col0 * E_;
    float acc[4][4][4] = {};
    for (int k0 = 0; k0 < E_; k0 += 16) {
        stage_bf(A + k0, E_, Ah, Al);
        stage_bf(Bw + k0, E_, Bh, Bl);
        __syncthreads();
        mma_slab3(Ah, Al, Bh, Bl, acc);
        __syncthreads();
    }
    const int lane = threadIdx.x & 31, warp = threadIdx.x >> 5;
    const int wm = warp >> 2, wn = warp & 3;
    const int gid = lane >> 2, t4 = lane & 3;
    #pragma unroll
    for (int mi = 0; mi < 4; mi++) {
        #pragma unroll
        for (int ni = 0; ni < 4; ni++) {
            int r = row0 + wm * 64 + mi * 16 + gid;
            int f = col0 + wn * 32 + ni * 8 + 2 * t4;
            float bb0 = bias[f], bb1 = bias[f + 1];
            *(float2*)&out[(size_t)r * E_ + f] =
                make_float2(acc[mi][ni][0] + bb0, acc[mi][ni][1] + bb1);
            *(float2*)&out[(size_t)(r + 8) * E_ + f] =
                make_float2(acc[mi][ni][2] + bb0, acc[mi][ni][3] + bb1);
        }
    }
}

// ---------------- launch ----------------
extern "C" void kernel_launch(void* const* d_in, const int* in_sizes, int n_in,
                              void* d_out, int out_size) {
    const float* fwd  = (const float*)d_in[0];
    const float* bwd  = (const float*)d_in[1];
    const int*   kpm  = (const int*)d_in[2];
    const float* W    = (const float*)d_in[3];   // (3E, E)
    const float* bias = (const float*)d_in[4];   // (3E,)
    const float* outw = (const float*)d_in[5];   // (E, E)
    const float* outb = (const float*)d_in[6];   // (E,)
    float* out = (float*)d_out;                       // (T,B,E)
    float* avg = out + (size_t)T_ * B_ * E_;          // (B,T,S)

    build_qin_kernel<<<(T_ * B_ * E_) / 1024, 256>>>(fwd, bwd);
    proj_q_kernel<<<dim3(E_ / 128, (T_ * B_) / 128), 256>>>(W, bias);
    proj_kv_kernel<<<dim3((2 * E_) / 128, (S_ * B_) / 128), 256>>>(fwd, bwd, W, bias);
    scores_kernel<<<dim3(9, T_ / 128, B_ * H_), 256>>>();
    softmax_avg_kernel<<<B_ * T_, 256>>>(kpm, avg);
    attn_kernel<<<dim3(T_ / 128, B_ * H_), 256>>>();
    out_proj_kernel<<<dim3(E_ / 128, (T_ * B_) / 128), 256>>>(outw, outb, out);
}

// round 15
// speedup vs baseline: 1.3055x; 1.0598x over previous
#include <cuda_runtime.h>
#include <cuda_bf16.h>
#include <math.h>
#include <stdint.h>

#define T_ 1024
#define B_ 8
#define E_ 512
#define H_ 8
#define D_ 64
#define S_ 2048
#define LDA 24
#define LDVB 72

// ---------------- scratch (device globals; no allocations) ----------------
__device__ float g_qin[T_ * B_ * E_];                 // (t,b,e)
__device__ float g_q[B_ * H_ * T_ * D_];              // (b,h,t,d)
__device__ float g_k[B_ * H_ * S_ * D_];              // (b,h,s,d)
__device__ float g_v[B_ * H_ * S_ * D_];              // (b,h,s,d)
__device__ float g_p[(size_t)B_ * H_ * T_ * S_];      // (b,h,t,s)
__device__ float g_attn[T_ * B_ * E_];                // (t,b, h*64+d)

// ---------------- bf16 split + mma helpers ----------------
__device__ __forceinline__ void mma16(float c[4], const uint32_t a[4],
                                      uint32_t b0, uint32_t b1) {
    asm volatile(
        "mma.sync.aligned.m16n8k16.row.col.f32.bf16.bf16.f32 "
        "{%0,%1,%2,%3},{%4,%5,%6,%7},{%8,%9},{%0,%1,%2,%3};"
        : "+f"(c[0]), "+f"(c[1]), "+f"(c[2]), "+f"(c[3])
        : "r"(a[0]), "r"(a[1]), "r"(a[2]), "r"(a[3]), "r"(b0), "r"(b1));
}

__device__ __forceinline__ void lda_frag(uint32_t f[4],
                                         const __nv_bfloat16 (*M)[LDA], int rbase) {
    int lane = threadIdx.x & 31;
    int lm = lane & 7, sel = lane >> 3;
    int row = rbase + lm + (sel & 1) * 8;
    int col = (sel >> 1) * 8;
    uint32_t addr = (uint32_t)__cvta_generic_to_shared(&M[row][col]);
    asm volatile("ldmatrix.sync.aligned.m8n8.x4.shared.b16 {%0,%1,%2,%3}, [%4];"
                 : "=r"(f[0]), "=r"(f[1]), "=r"(f[2]), "=r"(f[3]) : "r"(addr));
}

__device__ __forceinline__ void ldb_frag(uint32_t f[4],
                                         const __nv_bfloat16 (*M)[LDA], int nbase) {
    int lane = threadIdx.x & 31;
    int lm = lane & 7, sel = lane >> 3;
    int row = nbase + lm + (sel >> 1) * 8;
    int col = (sel & 1) * 8;
    uint32_t addr = (uint32_t)__cvta_generic_to_shared(&M[row][col]);
    asm volatile("ldmatrix.sync.aligned.m8n8.x4.shared.b16 {%0,%1,%2,%3}, [%4];"
                 : "=r"(f[0]), "=r"(f[1]), "=r"(f[2]), "=r"(f[3]) : "r"(addr));
}

__device__ __forceinline__ void ldvb_frag(uint32_t f[4],
                                          const __nv_bfloat16 (*M)[LDVB], int nbase) {
    int lane = threadIdx.x & 31;
    int lm = lane & 7, sel = lane >> 3;
    int row = lm + (sel & 1) * 8;          // k
    int col = nbase + (sel >> 1) * 8;      // n
    uint32_t addr = (uint32_t)__cvta_generic_to_shared(&M[row][col]);
    asm volatile("ldmatrix.sync.aligned.m8n8.x4.trans.shared.b16 {%0,%1,%2,%3}, [%4];"
                 : "=r"(f[0]), "=r"(f[1]), "=r"(f[2]), "=r"(f[3]) : "r"(addr));
}

// ---------------- slab staging: load fp32 + convert early ----------------
struct Slab { uint4 h, l; };

__device__ __forceinline__ Slab load_cvt(const float* __restrict__ src, int ld) {
    int r = threadIdx.x >> 1, c = (threadIdx.x & 1) << 3;
    const float* p = src + (size_t)r * ld + c;
    float4 v0 = *(const float4*)p;
    float4 v1 = *(const float4*)(p + 4);
    float v[8] = {v0.x, v0.y, v0.z, v0.w, v1.x, v1.y, v1.z, v1.w};
    uint32_t hu[4], lu[4];
    #pragma unroll
    for (int i = 0; i < 4; i++) {
        __nv_bfloat16 h0 = __float2bfloat16(v[2*i]);
        __nv_bfloat16 l0 = __float2bfloat16(v[2*i] - __bfloat162float(h0));
        __nv_bfloat16 h1 = __float2bfloat16(v[2*i+1]);
        __nv_bfloat16 l1 = __float2bfloat16(v[2*i+1] - __bfloat162float(h1));
        hu[i] = (uint32_t)__bfloat16_as_ushort(h0) | ((uint32_t)__bfloat16_as_ushort(h1) << 16);
        lu[i] = (uint32_t)__bfloat16_as_ushort(l0) | ((uint32_t)__bfloat16_as_ushort(l1) << 16);
    }
    Slab s;
    s.h = make_uint4(hu[0], hu[1], hu[2], hu[3]);
    s.l = make_uint4(lu[0], lu[1], lu[2], lu[3]);
    return s;
}

__device__ __forceinline__ void store_slab(const Slab& s,
                                           __nv_bfloat16 (*dh)[LDA],
                                           __nv_bfloat16 (*dl)[LDA]) {
    int r = threadIdx.x >> 1, c = (threadIdx.x & 1) << 3;
    *(uint4*)&dh[r][c] = s.h;
    *(uint4*)&dl[r][c] = s.l;
}

// 128x128 block, 3-pass bf16, one k16 slab already staged
__device__ __forceinline__ void mma_slab3(const __nv_bfloat16 (*Ah)[LDA],
                                          const __nv_bfloat16 (*Al)[LDA],
                                          const __nv_bfloat16 (*Bh)[LDA],
                                          const __nv_bfloat16 (*Bl)[LDA],
                                          float acc[4][4][4]) {
    const int warp = threadIdx.x >> 5;
    const int wm = warp >> 2, wn = warp & 3;
    uint32_t ah[4][4], al[4][4], bh[2][4], bl[2][4];
    #pragma unroll
    for (int mi = 0; mi < 4; mi++) {
        lda_frag(ah[mi], Ah, wm * 64 + mi * 16);
        lda_frag(al[mi], Al, wm * 64 + mi * 16);
    }
    #pragma unroll
    for (int np = 0; np < 2; np++) {
        ldb_frag(bh[np], Bh, wn * 32 + np * 16);
        ldb_frag(bl[np], Bl, wn * 32 + np * 16);
    }
    #pragma unroll
    for (int mi = 0; mi < 4; mi++) {
        #pragma unroll
        for (int ni = 0; ni < 4; ni++) {
            int np = ni >> 1, o = (ni & 1) << 1;
            mma16(acc[mi][ni], ah[mi], bh[np][o], bh[np][o + 1]);
            mma16(acc[mi][ni], ah[mi], bl[np][o], bl[np][o + 1]);
            mma16(acc[mi][ni], al[mi], bh[np][o], bh[np][o + 1]);
        }
    }
}

// ---------------- pipelined 128x128 gemm mainloop (double-buffered) ----------------
__device__ __forceinline__ void gemm_main(const float* __restrict__ A, int lda,
                                          const float* __restrict__ Bsrc, int ldb,
                                          int Kdim,
                                          __nv_bfloat16 (*Ah)[128][LDA],
                                          __nv_bfloat16 (*Al)[128][LDA],
                                          __nv_bfloat16 (*Bh)[128][LDA],
                                          __nv_bfloat16 (*Bl)[128][LDA],
                                          float acc[4][4][4]) {
    Slab sa = load_cvt(A, lda);
    Slab sb = load_cvt(Bsrc, ldb);
    store_slab(sa, Ah[0], Al[0]);
    store_slab(sb, Bh[0], Bl[0]);
    __syncthreads();
    int buf = 0;
    for (int k0 = 16;; k0 += 16) {
        bool more = k0 < Kdim;
        if (more) {
            sa = load_cvt(A + k0, lda);
            sb = load_cvt(Bsrc + k0, ldb);
        }
        mma_slab3(Ah[buf], Al[buf], Bh[buf], Bl[buf], acc);
        if (!more) break;
        buf ^= 1;
        store_slab(sa, Ah[buf], Al[buf]);
        store_slab(sb, Bh[buf], Bl[buf]);
        __syncthreads();
    }
}

// ---------------- q_in = shift(fwd,+1) + shift(bwd,-1), float4 ----------------
__global__ void build_qin_kernel(const float* __restrict__ fwd,
                                 const float* __restrict__ bwd) {
    int i4 = blockIdx.x * blockDim.x + threadIdx.x;
    int idx = i4 << 2;
    int t = idx / (B_ * E_);
    float4 v = make_float4(0.f, 0.f, 0.f, 0.f);
    if (t > 0) {
        float4 a = *(const float4*)(fwd + idx - B_ * E_);
        v.x += a.x; v.y += a.y; v.z += a.z; v.w += a.w;
    }
    if (t < T_ - 1) {
        float4 a = *(const float4*)(bwd + idx + B_ * E_);
        v.x += a.x; v.y += a.y; v.z += a.z; v.w += a.w;
    }
    *(float4*)(g_qin + idx) = v;
}

// ---------------- proj_q ----------------
__global__ __launch_bounds__(256, 2) void proj_q_kernel(const float* __restrict__ W,
                                                        const float* __restrict__ bias) {
    __shared__ __nv_bfloat16 Ah[2][128][LDA], Al[2][128][LDA], Bh[2][128][LDA], Bl[2][128][LDA];
    const int row0 = blockIdx.y * 128;
    const int col0 = blockIdx.x * 128;
    float acc[4][4][4] = {};
    gemm_main(g_qin + (size_t)row0 * E_, E_, W + (size_t)col0 * E_, E_, E_,
              Ah, Al, Bh, Bl, acc);
    const int lane = threadIdx.x & 31, warp = threadIdx.x >> 5;
    const int wm = warp >> 2, wn = warp & 3;
    const int gid = lane >> 2, t4 = lane & 3;
    #pragma unroll
    for (int mi = 0; mi < 4; mi++) {
        #pragma unroll
        for (int ni = 0; ni < 4; ni++) {
            int r = row0 + wm * 64 + mi * 16 + gid;
            int f = col0 + wn * 32 + ni * 8 + 2 * t4;
            int h = f >> 6, d = f & 63;
            float bb0 = bias[f], bb1 = bias[f + 1];
            int t = r >> 3, b = r & 7;
            *(float2*)&g_q[(size_t)(((b << 3) + h) * T_ + t) * D_ + d] =
                make_float2(acc[mi][ni][0] + bb0, acc[mi][ni][1] + bb1);
            *(float2*)&g_q[(size_t)(((b << 3) + h) * T_ + t + 1) * D_ + d] =
                make_float2(acc[mi][ni][2] + bb0, acc[mi][ni][3] + bb1);
        }
    }
}

// ---------------- proj_kv ----------------
__global__ __launch_bounds__(256, 2) void proj_kv_kernel(const float* __restrict__ fwd,
                                                         const float* __restrict__ bwd,
                                                         const float* __restrict__ W,
                                                         const float* __restrict__ bias) {
    __shared__ __nv_bfloat16 Ah[2][128][LDA], Al[2][128][LDA], Bh[2][128][LDA], Bl[2][128][LDA];
    const int row0 = blockIdx.y * 128;
    const int col0 = blockIdx.x * 128;
    const float* A = (row0 < T_ * B_) ? (fwd + (size_t)row0 * E_)
                                      : (bwd + (size_t)(row0 - T_ * B_) * E_);
    float acc[4][4][4] = {};
    gemm_main(A, E_, W + (size_t)(E_ + col0) * E_, E_, E_, Ah, Al, Bh, Bl, acc);
    const int lane = threadIdx.x & 31, warp = threadIdx.x >> 5;
    const int wm = warp >> 2, wn = warp & 3;
    const int gid = lane >> 2, t4 = lane & 3;
    float* dstbase = (col0 < E_) ? g_k : g_v;
    #pragma unroll
    for (int mi = 0; mi < 4; mi++) {
        #pragma unroll
        for (int ni = 0; ni < 4; ni++) {
            int r = row0 + wm * 64 + mi * 16 + gid;
            int f = col0 + wn * 32 + ni * 8 + 2 * t4;
            float bb0 = bias[E_ + f], bb1 = bias[E_ + f + 1];
            int f2 = f & (E_ - 1);
            int h = f2 >> 6, d = f2 & 63;
            int s = r >> 3, b = r & 7;
            *(float2*)&dstbase[((size_t)((b << 3) + h) * S_ + s) * D_ + d] =
                make_float2(acc[mi][ni][0] + bb0, acc[mi][ni][1] + bb1);
            *(float2*)&dstbase[((size_t)((b << 3) + h) * S_ + s + 1) * D_ + d] =
                make_float2(acc[mi][ni][2] + bb0, acc[mi][ni][3] + bb1);
        }
    }
}

// ---------------- scores: raw q.k, compacted grid ----------------
__global__ __launch_bounds__(256, 2) void scores_kernel() {
    const int bh = blockIdx.z;
    const int it = blockIdx.y;
    const int n = blockIdx.x;
    const int j = (n <= it) ? n : n + 7;
    const int t0 = it * 128;
    const int s0 = j * 128;
    __shared__ __nv_bfloat16 Ah[2][128][LDA], Al[2][128][LDA], Bh[2][128][LDA], Bl[2][128][LDA];
    float acc[4][4][4] = {};
    gemm_main(g_q + (size_t)bh * T_ * D_ + (size_t)t0 * D_, D_,
              g_k + (size_t)bh * S_ * D_ + (size_t)s0 * D_, D_, D_,
              Ah, Al, Bh, Bl, acc);
    float* P = g_p + (size_t)bh * T_ * S_;
    const int lane = threadIdx.x & 31, warp = threadIdx.x >> 5;
    const int wm = warp >> 2, wn = warp & 3;
    const int gid = lane >> 2, t4 = lane & 3;
    #pragma unroll
    for (int mi = 0; mi < 4; mi++) {
        #pragma unroll
        for (int ni = 0; ni < 4; ni++) {
            int r = t0 + wm * 64 + mi * 16 + gid;
            int c = s0 + wn * 32 + ni * 8 + 2 * t4;
            *(float2*)&P[(size_t)r * S_ + c] = make_float2(acc[mi][ni][0], acc[mi][ni][1]);
            *(float2*)&P[(size_t)(r + 8) * S_ + c] = make_float2(acc[mi][ni][2], acc[mi][ni][3]);
        }
    }
}

// ---------------- softmax per (b,t) + head-mean; band-skip both ways ----------------
__device__ __forceinline__ float blk_reduce(float v, bool is_max, float* red) {
    #pragma unroll
    for (int o = 16; o; o >>= 1) {
        float w = __shfl_xor_sync(0xffffffffu, v, o);
        v = is_max ? fmaxf(v, w) : v + w;
    }
    if ((threadIdx.x & 31) == 0) red[threadIdx.x >> 5] = v;
    __syncthreads();
    if (threadIdx.x < 32) {
        float x = (threadIdx.x < 8) ? red[threadIdx.x] : (is_max ? -1e30f : 0.f);
        #pragma unroll
        for (int o = 4; o; o >>= 1) {
            float w = __shfl_xor_sync(0xffffffffu, x, o);
            x = is_max ? fmaxf(x, w) : x + w;
        }
        if (threadIdx.x == 0) red[0] = x;
    }
    __syncthreads();
    float r = red[0];
    __syncthreads();
    return r;
}

__global__ void softmax_avg_kernel(const int* __restrict__ kpm,
                                   float* __restrict__ avg_out) {
    __shared__ float red[32];
    const int bt = blockIdx.x;
    const int b = bt >> 10;
    const int t = bt & (T_ - 1);
    const int t0 = t & ~127;
    const int tid = threadIdx.x;
    bool msk[2][4];
    bool wr[2], band[2];
    #pragma unroll
    for (int i = 0; i < 2; i++) {
        int s4 = (tid << 2) + (i << 10);
        wr[i] = (s4 < t0 + 128) || (s4 >= t0 + 1024);
        band[i] = (s4 >= t) && (s4 + 3 <= t + T_);
        #pragma unroll
        for (int e = 0; e < 4; e++) {
            int s = s4 + e;
            msk[i][e] = (s >= t && s <= t + T_) || (kpm[b * T_ + (s & (T_ - 1))] != 0);
        }
    }
    float avg[2][4] = {};
    for (int h = 0; h < H_; h++) {
        float* row = g_p + ((size_t)(((b << 3) + h) * T_ + t)) * S_;
        float vreg[2][4];
        float m = -1e30f;
        #pragma unroll
        for (int i = 0; i < 2; i++) {
            int s4 = (tid << 2) + (i << 10);
            float4 v = band[i] ? make_float4(0.f, 0.f, 0.f, 0.f)
                               : *(const float4*)(row + s4);
            float tmp[4] = {v.x, v.y, v.z, v.w};
            #pragma unroll
            for (int e = 0; e < 4; e++) {
                float x = msk[i][e] ? -1e30f : tmp[e];
                vreg[i][e] = x;
                m = fmaxf(m, x);
            }
        }
        m = blk_reduce(m, true, red);
        float sum = 0.f;
        #pragma unroll
        for (int i = 0; i < 2; i++)
            #pragma unroll
            for (int e = 0; e < 4; e++) {
                if (!msk[i][e]) { vreg[i][e] = __expf(vreg[i][e] - m); sum += vreg[i][e]; }
                else vreg[i][e] = 0.f;
            }
        sum = blk_reduce(sum, false, red);
        float inv = 1.f / sum;
        #pragma unroll
        for (int i = 0; i < 2; i++) {
            int s4 = (tid << 2) + (i << 10);
            float p0 = vreg[i][0] * inv, p1 = vreg[i][1] * inv;
            float p2 = vreg[i][2] * inv, p3 = vreg[i][3] * inv;
            if (wr[i])
                *(float4*)(row + s4) = make_float4(p0, p1, p2, p3);
            avg[i][0] += p0; avg[i][1] += p1; avg[i][2] += p2; avg[i][3] += p3;
        }
    }
    size_t o = (size_t)bt * S_;
    #pragma unroll
    for (int i = 0; i < 2; i++) {
        int s4 = (tid << 2) + (i << 10);
        *(float4*)(avg_out + o + s4) = make_float4(avg[i][0] * 0.125f, avg[i][1] * 0.125f,
                                                   avg[i][2] * 0.125f, avg[i][3] * 0.125f);
    }
}

// ---------------- attn = p @ v (3-pass bf16, pipelined, skip zero band) ----------------
struct VSlab { uint2 h, l; };

__device__ __forceinline__ VSlab load_cvt_v(const float* __restrict__ V, int k0) {
    int r = threadIdx.x >> 4, c = (threadIdx.x & 15) << 2;
    float4 v = *(const float4*)(V + (size_t)(k0 + r) * D_ + c);
    float vv[4] = {v.x, v.y, v.z, v.w};
    uint32_t hu[2], lu[2];
    #pragma unroll
    for (int i = 0; i < 2; i++) {
        __nv_bfloat16 h0 = __float2bfloat16(vv[2*i]);
        __nv_bfloat16 l0 = __float2bfloat16(vv[2*i] - __bfloat162float(h0));
        __nv_bfloat16 h1 = __float2bfloat16(vv[2*i+1]);
        __nv_bfloat16 l1 = __float2bfloat16(vv[2*i+1] - __bfloat162float(h1));
        hu[i] = (uint32_t)__bfloat16_as_ushort(h0) | ((uint32_t)__bfloat16_as_ushort(h1) << 16);
        lu[i] = (uint32_t)__bfloat16_as_ushort(l0) | ((uint32_t)__bfloat16_as_ushort(l1) << 16);
    }
    VSlab s;
    s.h = make_uint2(hu[0], hu[1]);
    s.l = make_uint2(lu[0], lu[1]);
    return s;
}

__device__ __forceinline__ void store_vslab(const VSlab& s,
                                            __nv_bfloat16 (*dh)[LDVB],
                                            __nv_bfloat16 (*dl)[LDVB]) {
    int r = threadIdx.x >> 4, c = (threadIdx.x & 15) << 2;
    *(uint2*)&dh[r][c] = s.h;
    *(uint2*)&dl[r][c] = s.l;
}

__global__ __launch_bounds__(256, 2) void attn_kernel() {
    __shared__ __nv_bfloat16 Ph[2][128][LDA], Pl[2][128][LDA];
    __shared__ __nv_bfloat16 Vh[2][16][LDVB], Vl[2][16][LDVB];
    const int t0 = blockIdx.x * 128;
    const int bh = blockIdx.y;
    const float* P = g_p + (size_t)bh * T_ * S_ + (size_t)t0 * S_;
    const float* V = g_v + (size_t)bh * S_ * D_;
    const int tid = threadIdx.x;
    const int lane = tid & 31, warp = tid >> 5;
    const int wm = warp >> 1, wn = warp & 1;   // warp tile: 32(t) x 32(d)
    const int gid = lane >> 2, t4 = lane & 3;
    float acc[2][4][4] = {};
    // active k0 sequence: 0,16,... skipping [t0+128, t0+1008]
    int k0 = 0;
    Slab ps = load_cvt(P + k0, S_);
    VSlab vs = load_cvt_v(V, k0);
    store_slab(ps, Ph[0], Pl[0]);
    store_vslab(vs, Vh[0], Vl[0]);
    __syncthreads();
    int buf = 0;
    while (true) {
        int k1 = (k0 + 16 == t0 + 128) ? t0 + 1024 : k0 + 16;
        bool more = k1 < S_;
        if (more) {
            ps = load_cvt(P + k1, S_);
            vs = load_cvt_v(V, k1);
        }
        // MMA on current buffer
        {
            uint32_t ah[2][4], al[2][4], bh2[2][4], bl2[2][4];
            #pragma unroll
            for (int mi = 0; mi < 2; mi++) {
                lda_frag(ah[mi], Ph[buf], wm * 32 + mi * 16);
                lda_frag(al[mi], Pl[buf], wm * 32 + mi * 16);
            }
            #pragma unroll
            for (int np = 0; np < 2; np++) {
                ldvb_frag(bh2[np], Vh[buf], wn * 32 + np * 16);
                ldvb_frag(bl2[np], Vl[buf], wn * 32 + np * 16);
            }
            #pragma unroll
            for (int mi = 0; mi < 2; mi++) {
                #pragma unroll
                for (int ni = 0; ni < 4; ni++) {
                    int np = ni >> 1, o = (ni & 1) << 1;
                    mma16(acc[mi][ni], ah[mi], bh2[np][o], bh2[np][o + 1]);
                    mma16(acc[mi][ni], ah[mi], bl2[np][o], bl2[np][o + 1]);
                    mma16(acc[mi][ni], al[mi], bh2[np][o], bh2[np][o + 1]);
                }
            }
        }
        if (!more) break;
        buf ^= 1;
        store_slab(ps, Ph[buf], Pl[buf]);
        store_vslab(vs, Vh[buf], Vl[buf]);
        __syncthreads();
        k0 = k1;
    }
    const int b = bh >> 3, h = bh & 7;
    #pragma unroll
    for (int mi = 0; mi < 2; mi++) {
        #pragma unroll
        for (int ni = 0; ni < 4; ni++) {
            int t = t0 + wm * 32 + mi * 16 + gid;
            int d = wn * 32 + ni * 8 + 2 * t4;
            *(float2*)&g_attn[(size_t)((t << 3) + b) * E_ + (h << 6) + d] =
                make_float2(acc[mi][ni][0], acc[mi][ni][1]);
            *(float2*)&g_attn[(size_t)(((t + 8) << 3) + b) * E_ + (h << 6) + d] =
                make_float2(acc[mi][ni][2], acc[mi][ni][3]);
        }
    }
}

// ---------------- out = attn @ out_w^T + out_b (3-pass bf16) ----------------
__global__ __launch_bounds__(256, 2) void out_proj_kernel(const float* __restrict__ W,
                                                          const float* __restrict__ bias,
                                                          float* __restrict__ out) {
    __shared__ __nv_bfloat16 Ah[2][128][LDA], Al[2][128][LDA], Bh[2][128][LDA], Bl[2][128][LDA];
    const int row0 = blockIdx.y * 128;
    const int col0 = blockIdx.x * 128;
    float acc[4][4][4] = {};
    gemm_main(g_attn + (size_t)row0 * E_, E_, W + (size_t)col0 * E_, E_, E_,
              Ah, Al, Bh, Bl, acc);
    const int lane = threadIdx.x & 31, warp = threadIdx.x >> 5;
    const int wm = warp >> 2, wn = warp & 3;
    const int gid = lane >> 2, t4 = lane & 3;
    #pragma unroll
    for (int mi = 0; mi < 4; mi++) {
        #pragma unroll
        for (int ni = 0; ni < 4; ni++) {
            int r = row0 + wm * 64 + mi * 16 + gid;
            int f = col0 + wn * 32 + ni * 8 + 2 * t4;
            float bb0 = bias[f], bb1 = bias[f + 1];
            *(float2*)&out[(size_t)r * E_ + f] =
                make_float2(acc[mi][ni][0] + bb0, acc[mi][ni][1] + bb1);
            *(float2*)&out[(size_t)(r + 8) * E_ + f] =
                make_float2(acc[mi][ni][2] + bb0, acc[mi][ni][3] + bb1);
        }
    }
}

// ---------------- launch ----------------
extern "C" void kernel_launch(void* const* d_in, const int* in_sizes, int n_in,
                              void* d_out, int out_size) {
    const float* fwd  = (const float*)d_in[0];
    const float* bwd  = (const float*)d_in[1];
    const int*   kpm  = (const int*)d_in[2];
    const float* W    = (const float*)d_in[3];   // (3E, E)
    const float* bias = (const float*)d_in[4];   // (3E,)
    const float* outw = (const float*)d_in[5];   // (E, E)
    const float* outb = (const float*)d_in[6];   // (E,)
    float* out = (float*)d_out;                       // (T,B,E)
    float* avg = out + (size_t)T_ * B_ * E_;          // (B,T,S)

    build_qin_kernel<<<(T_ * B_ * E_) / 1024, 256>>>(fwd, bwd);
    proj_q_kernel<<<dim3(E_ / 128, (T_ * B_) / 128), 256>>>(W, bias);
    proj_kv_kernel<<<dim3((2 * E_) / 128, (S_ * B_) / 128), 256>>>(fwd, bwd, W, bias);
    scores_kernel<<<dim3(9, T_ / 128, B_ * H_), 256>>>();
    softmax_avg_kernel<<<B_ * T_, 256>>>(kpm, avg);
    attn_kernel<<<dim3(T_ / 128, B_ * H_), 256>>>();
    out_proj_kernel<<<dim3(E_ / 128, (T_ * B_) / 128), 256>>>(outw, outb, out);
}